// round 4
// baseline (speedup 1.0000x reference)
#include <cuda_runtime.h>
#include <cstdint>
#include <cstddef>

#define BB 128
#define TT 128
#define HH 1024
#define H3 3072
#define NBLK 128   // persistent grid size (32 x 4)

// Scratch (static device globals -- no dynamic allocation allowed).
__device__ float    g_xp[50331648ULL];          // [T][B][3H] fp32 (192 MB)
__device__ uint32_t g_whtf[2ULL * 3 * HH * HH]; // Wh pre-converted to tf32 (25 MB)
__device__ float    g_hbuf[2 * BB * HH];        // double-buffered h (fp32)
__device__ uint32_t g_htf[2 * BB * HH];         // double-buffered h (tf32)
__device__ unsigned g_bar_cnt;                  // grid barrier (self-resetting)
__device__ unsigned g_bar_phs;

__device__ __forceinline__ uint32_t f2tf(float f) {
    uint32_t u;
    asm("cvt.rna.tf32.f32 %0, %1;" : "=r"(u) : "f"(f));
    return u;
}

__device__ __forceinline__ void mma_tf32(float d[4], const uint32_t a[4], const uint32_t b[2]) {
    asm volatile(
        "mma.sync.aligned.m16n8k8.row.col.f32.tf32.tf32.f32 "
        "{%0,%1,%2,%3}, {%4,%5,%6,%7}, {%8,%9}, {%0,%1,%2,%3};"
        : "+f"(d[0]), "+f"(d[1]), "+f"(d[2]), "+f"(d[3])
        : "r"(a[0]), "r"(a[1]), "r"(a[2]), "r"(a[3]), "r"(b[0]), "r"(b[1]));
}

__device__ __forceinline__ void ldsm4(uint32_t& r0, uint32_t& r1, uint32_t& r2, uint32_t& r3,
                                      uint32_t addr) {
    asm volatile("ldmatrix.sync.aligned.m8n8.x4.shared.b16 {%0,%1,%2,%3}, [%4];"
                 : "=r"(r0), "=r"(r1), "=r"(r2), "=r"(r3) : "r"(addr));
}

// Grid barrier: all NBLK CTAs co-resident (1 per SM). Release semantics via
// __threadfence before arrive; acquire via __threadfence after observing phase.
__device__ __forceinline__ void grid_sync_dev() {
    __syncthreads();
    if (threadIdx.x == 0) {
        volatile unsigned* vphs = &g_bar_phs;
        unsigned ph = *vphs;
        __threadfence();
        unsigned ticket = atomicAdd(&g_bar_cnt, 1u);
        if (ticket == NBLK - 1) {
            *((volatile unsigned*)&g_bar_cnt) = 0u;
            __threadfence();
            *vphs = ph + 1u;
        } else {
            while (*vphs == ph) { __nanosleep(64); }
            __threadfence();
        }
    }
    __syncthreads();
}

// ---------------------------------------------------------------------------
// Elementwise fp32 -> tf32 conversion (vectorized x4).
// ---------------------------------------------------------------------------
__global__ void cvt_tf32_kernel(const float* __restrict__ src, uint32_t* __restrict__ dst, int n4)
{
    int i = blockIdx.x * blockDim.x + threadIdx.x;
    if (i < n4) {
        float4 v = ((const float4*)src)[i];
        uint4 o;
        o.x = f2tf(v.x); o.y = f2tf(v.y); o.z = f2tf(v.z); o.w = f2tf(v.w);
        ((uint4*)dst)[i] = o;
    }
}

// ---------------------------------------------------------------------------
// xproj: C[m][n] = sum_k A[m][k] * W[n][k] + bias[n]   (unchanged)
// ---------------------------------------------------------------------------
#define XST 20

__global__ __launch_bounds__(256) void xproj_kernel(
    const float* __restrict__ cur, const float* __restrict__ W,
    const float* __restrict__ bias, float* __restrict__ xp)
{
    __shared__ uint32_t As[2][128 * XST];
    __shared__ uint32_t Bs[2][128 * XST];

    const int tid  = threadIdx.x;
    const int lane = tid & 31;
    const int wid  = tid >> 5;
    const int wm   = (wid >> 2) * 64;
    const int wn   = (wid & 3) * 32;
    const int m0   = blockIdx.y * 128;
    const int n0   = blockIdx.x * 128;

    const float* gp[4];
    int soff[2];
    #pragma unroll
    for (int i = 0; i < 2; i++) {
        int idx = tid + i * 256;
        int row = idx >> 2, kv = idx & 3;
        int m = m0 + row;
        int b = m & (BB - 1);
        int t = m >> 7;
        gp[i]     = cur + ((size_t)b * TT + t) * HH + kv * 4;
        gp[2 + i] = W + (size_t)(n0 + row) * HH + kv * 4;
        soff[i]   = row * XST + kv * 4;
    }

    float acc[4][4][4];
    #pragma unroll
    for (int a = 0; a < 4; a++)
        #pragma unroll
        for (int b = 0; b < 4; b++)
            #pragma unroll
            for (int c = 0; c < 4; c++) acc[a][b][c] = 0.f;

    float4 rv[4];
    #pragma unroll
    for (int i = 0; i < 4; i++) rv[i] = *(const float4*)(gp[i]);
    #pragma unroll
    for (int i = 0; i < 2; i++) {
        uint32_t* p = &As[0][soff[i]];
        p[0] = f2tf(rv[i].x); p[1] = f2tf(rv[i].y); p[2] = f2tf(rv[i].z); p[3] = f2tf(rv[i].w);
        uint32_t* q = &Bs[0][soff[i]];
        q[0] = f2tf(rv[2+i].x); q[1] = f2tf(rv[2+i].y); q[2] = f2tf(rv[2+i].z); q[3] = f2tf(rv[2+i].w);
    }
    __syncthreads();

    const int NKT = HH / 16;
    for (int kt = 0; kt < NKT; kt++) {
        int cb = kt & 1;
        if (kt + 1 < NKT) {
            #pragma unroll
            for (int i = 0; i < 4; i++)
                rv[i] = *(const float4*)(gp[i] + (kt + 1) * 16);
        }
        #pragma unroll
        for (int kk = 0; kk < 2; kk++) {
            uint32_t af[4][4], bf[4][2];
            const int c  = kk * 8 + (lane & 3);
            const int rA = wm + (lane >> 2);
            #pragma unroll
            for (int mt = 0; mt < 4; mt++) {
                int r = rA + mt * 16;
                af[mt][0] = As[cb][r * XST + c];
                af[mt][1] = As[cb][(r + 8) * XST + c];
                af[mt][2] = As[cb][r * XST + c + 4];
                af[mt][3] = As[cb][(r + 8) * XST + c + 4];
            }
            const int rB = wn + (lane >> 2);
            #pragma unroll
            for (int nt = 0; nt < 4; nt++) {
                int r = rB + nt * 8;
                bf[nt][0] = Bs[cb][r * XST + c];
                bf[nt][1] = Bs[cb][r * XST + c + 4];
            }
            #pragma unroll
            for (int mt = 0; mt < 4; mt++)
                #pragma unroll
                for (int nt = 0; nt < 4; nt++)
                    mma_tf32(acc[mt][nt], af[mt], bf[nt]);
        }
        if (kt + 1 < NKT) {
            int nb = cb ^ 1;
            #pragma unroll
            for (int i = 0; i < 2; i++) {
                uint32_t* p = &As[nb][soff[i]];
                p[0] = f2tf(rv[i].x); p[1] = f2tf(rv[i].y); p[2] = f2tf(rv[i].z); p[3] = f2tf(rv[i].w);
                uint32_t* q = &Bs[nb][soff[i]];
                q[0] = f2tf(rv[2+i].x); q[1] = f2tf(rv[2+i].y); q[2] = f2tf(rv[2+i].z); q[3] = f2tf(rv[2+i].w);
            }
            __syncthreads();
        }
    }

    #pragma unroll
    for (int mt = 0; mt < 4; mt++) {
        int r = m0 + wm + mt * 16 + (lane >> 2);
        #pragma unroll
        for (int nt = 0; nt < 4; nt++) {
            int cg = n0 + wn + nt * 8 + (lane & 3) * 2;
            float2 bz = *(const float2*)(bias + cg);
            float2 v0 = make_float2(acc[mt][nt][0] + bz.x, acc[mt][nt][1] + bz.y);
            float2 v1 = make_float2(acc[mt][nt][2] + bz.x, acc[mt][nt][3] + bz.y);
            *(float2*)(xp + (size_t)r * H3 + cg)       = v0;
            *(float2*)(xp + (size_t)(r + 8) * H3 + cg) = v1;
        }
    }
}

// ---------------------------------------------------------------------------
// Persistent recurrence kernel: all 128 timesteps of one layer in a single
// launch. 128 co-resident CTAs (32 o-tiles x 4 b-tiles), grid barrier between
// steps. Inner GEMM identical to R3's validated 12-warp / 8-stage pipeline.
// ---------------------------------------------------------------------------
#define NST   8
#define ROWST 20                   // u32 per smem row (16 + 4 pad)
#define STGU  (128 * ROWST)        // u32 per stage
#define STGB  (STGU * 4)           // bytes per stage (10240)

__global__ __launch_bounds__(384) void persist_kernel(
    const uint32_t* __restrict__ Wh_tf,     // tf32 [3,H,H] (layer slice)
    const float*    __restrict__ bhv,       // [3,H]
    const float*    __restrict__ xp,        // [T,B,3H]
    float*          __restrict__ y,         // [B,T,H]
    float* hA, float* hB, uint32_t* hAt, uint32_t* hBt)
{
    extern __shared__ uint32_t sm[];        // NST * STGU (80 KB)

    const int tid  = threadIdx.x;
    const int lane = tid & 31;
    const int wid  = tid >> 5;              // 0..11
    const int o0   = blockIdx.x * 32;
    const int b0   = blockIdx.y * 32;
    const int wm   = (wid / 6) * 16;        // 0 or 16
    const int wn   = (wid % 6) * 16;        // 0..80

    uint32_t smbase;
    asm("{.reg .u64 tt; cvta.to.shared.u64 tt, %1; cvt.u32.u64 %0, tt;}"
        : "=r"(smbase) : "l"(&sm[0]));

    // cp.async chunk mapping (512 x 16B chunks / stage):
    //   tid <  128 : h row chunk (row tid>>2, kv tid&3)   + extra Wh chunk gs1
    //   tid >= 128 : Wh row chunk (rows 0..63)
    size_t   hOff = 0;                      // element offset into h tf32 buffer
    const uint32_t* wsrc0 = nullptr;        // Wh source (tid>=128)
    uint32_t sd0;
    const uint32_t* gs1 = nullptr; uint32_t sd1 = 0;
    {
        if (tid < 128) {
            int row = tid >> 2, kv = tid & 3;
            hOff = (size_t)(b0 + row) * HH + kv * 4;
            sd0  = (uint32_t)(row * ROWST + kv * 4) * 4;
            int j = tid + 256;              // Wh rows 64..95
            int wrow = j >> 2, wkv = j & 3;
            gs1 = Wh_tf + ((size_t)(wrow >> 5) * HH + o0 + (wrow & 31)) * HH + wkv * 4;
            sd1 = (uint32_t)((32 + wrow) * ROWST + wkv * 4) * 4;
        } else {
            int j = tid - 128;              // Wh rows 0..63
            int wrow = j >> 2, wkv = j & 3;
            wsrc0 = Wh_tf + ((size_t)(wrow >> 5) * HH + o0 + (wrow & 31)) * HH + wkv * 4;
            sd0   = (uint32_t)((32 + wrow) * ROWST + wkv * 4) * 4;
        }
    }

    // Invariant ldmatrix address components.
    const int g  = lane >> 3;
    const int r8 = lane & 7;
    const uint32_t aoff = (uint32_t)((wm + (g & 1) * 8 + r8) * ROWST + (g >> 1) * 4) * 4;
    const uint32_t boff = (uint32_t)((32 + wn + (g >> 1) * 8 + r8) * ROWST + (g & 1) * 4) * 4;

    for (int t = 0; t < TT; t++) {
        const uint32_t* hsrc_tf = (t & 1) ? hBt : hAt;
        const float*    hprev   = (t & 1) ? hB  : hA;
        float*          hnext   = (t & 1) ? hA  : hB;
        uint32_t*       hnxt_tf = (t & 1) ? hAt : hBt;
        const float*    xp_t    = xp + (size_t)t * BB * H3;

        const uint32_t* gs0 = (tid < 128) ? (hsrc_tf + hOff) : wsrc0;

        // Prologue: fill stage pairs 0,1,2.
        #pragma unroll
        for (int p = 0; p < 3; p++) {
            #pragma unroll
            for (int ss = 0; ss < 2; ss++) {
                int s = 2 * p + ss;
                uint32_t sb = smbase + (uint32_t)(s & (NST - 1)) * STGB;
                asm volatile("cp.async.cg.shared.global [%0], [%1], 16;"
                             :: "r"(sb + sd0), "l"(gs0 + s * 16));
                if (tid < 128)
                    asm volatile("cp.async.cg.shared.global [%0], [%1], 16;"
                                 :: "r"(sb + sd1), "l"(gs1 + s * 16));
            }
            asm volatile("cp.async.commit_group;");
        }

        float acc[2][4];
        #pragma unroll
        for (int nt = 0; nt < 2; nt++)
            #pragma unroll
            for (int c = 0; c < 4; c++) acc[nt][c] = 0.f;

        const int NPAIR = HH / 32;  // 32
        for (int p = 0; p < NPAIR; p++) {
            asm volatile("cp.async.wait_group 2;");
            __syncthreads();

            if (p < NPAIR - 3) {
                #pragma unroll
                for (int ss = 0; ss < 2; ss++) {
                    int s = 2 * (p + 3) + ss;
                    uint32_t sb = smbase + (uint32_t)(s & (NST - 1)) * STGB;
                    asm volatile("cp.async.cg.shared.global [%0], [%1], 16;"
                                 :: "r"(sb + sd0), "l"(gs0 + s * 16));
                    if (tid < 128)
                        asm volatile("cp.async.cg.shared.global [%0], [%1], 16;"
                                     :: "r"(sb + sd1), "l"(gs1 + s * 16));
                }
            }
            asm volatile("cp.async.commit_group;");

            #pragma unroll
            for (int ss = 0; ss < 2; ss++) {
                uint32_t sb = smbase + (uint32_t)((2 * p + ss) & (NST - 1)) * STGB;
                #pragma unroll
                for (int kk = 0; kk < 2; kk++) {
                    uint32_t kb = (uint32_t)kk * 32;
                    uint32_t af[4], bf[4];
                    ldsm4(af[0], af[1], af[2], af[3], sb + aoff + kb);
                    ldsm4(bf[0], bf[1], bf[2], bf[3], sb + boff + kb);
                    mma_tf32(acc[0], af, &bf[0]);
                    mma_tf32(acc[1], af, &bf[2]);
                }
            }
        }
        asm volatile("cp.async.wait_group 0;");
        __syncthreads();  // fragment reads done -> safe to alias smem

        // Scatter accumulators: Cs[32][100] fp32 (aliases stages 0-1).
        float* Cs = (float*)sm;
        #pragma unroll
        for (int nt = 0; nt < 2; nt++) {
            int r = wm + (lane >> 2);
            int c = wn + nt * 8 + (lane & 3) * 2;
            Cs[r * 100 + c]           = acc[nt][0];
            Cs[r * 100 + c + 1]       = acc[nt][1];
            Cs[(r + 8) * 100 + c]     = acc[nt][2];
            Cs[(r + 8) * 100 + c + 1] = acc[nt][3];
        }
        __syncthreads();

        // Gate fusion: threads 0..255 -> (batch b, 4 consecutive units).
        if (tid < 256) {
            const int b  = tid >> 3;
            const int oq = (tid & 7) * 4;
            const int bg = b0 + b;
            const int og = o0 + oq;
            const float* xpr = xp_t + (size_t)bg * H3;

            float4 xr4 = *(const float4*)(xpr + og);
            float4 xz4 = *(const float4*)(xpr + HH + og);
            float4 xn4 = *(const float4*)(xpr + 2 * HH + og);
            float4 br4 = *(const float4*)(bhv + og);
            float4 bz4 = *(const float4*)(bhv + HH + og);
            float4 bn4 = *(const float4*)(bhv + 2 * HH + og);
            float4 hp4 = *(const float4*)(hprev + (size_t)bg * HH + og);

            float hv[4];
            #pragma unroll
            for (int j = 0; j < 4; j++) {
                int o = oq + j;
                float hr = Cs[b * 100 + o]      + ((const float*)&br4)[j];
                float hz = Cs[b * 100 + 32 + o] + ((const float*)&bz4)[j];
                float hn = Cs[b * 100 + 64 + o] + ((const float*)&bn4)[j];
                float r  = 1.f / (1.f + __expf(-(((const float*)&xr4)[j] + hr)));
                float z  = 1.f / (1.f + __expf(-(((const float*)&xz4)[j] + hz)));
                float n  = tanhf(((const float*)&xn4)[j] + r * hn);
                hv[j] = (1.f - z) * n + z * ((const float*)&hp4)[j];
            }
            *(float4*)(hnext + (size_t)bg * HH + og) = make_float4(hv[0], hv[1], hv[2], hv[3]);
            *(float4*)(y + ((size_t)bg * TT + t) * HH + og) = make_float4(hv[0], hv[1], hv[2], hv[3]);
            uint4 tf;
            tf.x = f2tf(hv[0]); tf.y = f2tf(hv[1]); tf.z = f2tf(hv[2]); tf.w = f2tf(hv[3]);
            *(uint4*)(hnxt_tf + (size_t)bg * HH + og) = tf;
        }

        if (t + 1 < TT) grid_sync_dev();
    }
}

// ---------------------------------------------------------------------------
extern "C" void kernel_launch(void* const* d_in, const int* in_sizes, int n_in,
                              void* d_out, int out_size)
{
    (void)in_sizes; (void)n_in; (void)out_size;
    const float* x   = (const float*)d_in[0];  // [B,T,H]
    const float* h0  = (const float*)d_in[1];  // [L,B,H]
    const float* Wx  = (const float*)d_in[2];  // [L,3,H,H]
    const float* Wh  = (const float*)d_in[3];  // [L,3,H,H]
    const float* bx  = (const float*)d_in[4];  // [L,3,H]
    const float* bh  = (const float*)d_in[5];  // [L,3,H]
    float* out   = (float*)d_out;              // [B,T,H] then [L,B,H]
    float* hlast = out + (size_t)BB * TT * HH;

    float*    xp   = nullptr;
    float*    hbuf = nullptr;
    uint32_t* whtf = nullptr;
    uint32_t* htf  = nullptr;
    cudaGetSymbolAddress((void**)&xp,   g_xp);
    cudaGetSymbolAddress((void**)&hbuf, g_hbuf);
    cudaGetSymbolAddress((void**)&whtf, g_whtf);
    cudaGetSymbolAddress((void**)&htf,  g_htf);
    float*    hA  = hbuf;
    float*    hB  = hbuf + BB * HH;
    uint32_t* hAt = htf;
    uint32_t* hBt = htf + BB * HH;

    cudaFuncSetAttribute(persist_kernel,
                         cudaFuncAttributeMaxDynamicSharedMemorySize, NST * STGB);

    // Pre-convert Wh (both layers) to tf32.
    {
        int n4 = 2 * 3 * HH * HH / 4;
        cvt_tf32_kernel<<<n4 / 256, 256>>>(Wh, whtf, n4);
    }

    dim3 xgrid(H3 / 128, (BB * TT) / 128);  // (24, 128)
    dim3 pgrid(HH / 32, BB / 32);           // (32, 4) = 128 CTAs, all resident

    for (int l = 0; l < 2; l++) {
        const float* cur = (l == 0) ? x : out;  // layer-1 input = layer-0 output
        xproj_kernel<<<xgrid, 256>>>(cur, Wx + (size_t)l * 3 * HH * HH,
                                     bx + (size_t)l * 3 * HH, xp);
        cudaMemcpyAsync(hA, h0 + (size_t)l * BB * HH, (size_t)BB * HH * sizeof(float),
                        cudaMemcpyDeviceToDevice);
        {
            int n4 = BB * HH / 4;
            cvt_tf32_kernel<<<n4 / 256, 256>>>(h0 + (size_t)l * BB * HH, hAt, n4);
        }
        persist_kernel<<<pgrid, 384, NST * STGB>>>(
            whtf + (size_t)l * 3 * HH * HH, bh + (size_t)l * 3 * HH,
            xp, out, hA, hB, hAt, hBt);
        // T=128 even -> final hidden ends up in hA
        cudaMemcpyAsync(hlast + (size_t)l * BB * HH, hA, (size_t)BB * HH * sizeof(float),
                        cudaMemcpyDeviceToDevice);
    }
}

// round 5
// speedup vs baseline: 1.7554x; 1.7554x over previous
#include <cuda_runtime.h>
#include <cuda_fp16.h>
#include <cstdint>
#include <cstddef>

#define BB 128
#define TT 128
#define HH 1024
#define H3 3072
#define NBLK 128   // persistent grid size (32 x 4)

// Scratch (static device globals -- no dynamic allocation allowed).
__device__ float  g_xp[50331648ULL];          // [T][B][3H] fp32 (192 MB)
__device__ __half g_whh[2ULL * 3 * HH * HH];  // Wh pre-converted to fp16 (12.6 MB)
__device__ float  g_hbuf[2 * BB * HH];        // double-buffered h (fp32, exact carrier)
__device__ __half g_hh[2 * BB * HH];          // double-buffered h (fp16, mma operand)
__device__ unsigned g_bar_cnt;                // grid barrier (self-resetting)
__device__ unsigned g_bar_phs;

__device__ __forceinline__ void mma_f16(float d[4], const uint32_t a[4], const uint32_t b[2]) {
    asm volatile(
        "mma.sync.aligned.m16n8k16.row.col.f32.f16.f16.f32 "
        "{%0,%1,%2,%3}, {%4,%5,%6,%7}, {%8,%9}, {%0,%1,%2,%3};"
        : "+f"(d[0]), "+f"(d[1]), "+f"(d[2]), "+f"(d[3])
        : "r"(a[0]), "r"(a[1]), "r"(a[2]), "r"(a[3]), "r"(b[0]), "r"(b[1]));
}

__device__ __forceinline__ void ldsm4(uint32_t& r0, uint32_t& r1, uint32_t& r2, uint32_t& r3,
                                      uint32_t addr) {
    asm volatile("ldmatrix.sync.aligned.m8n8.x4.shared.b16 {%0,%1,%2,%3}, [%4];"
                 : "=r"(r0), "=r"(r1), "=r"(r2), "=r"(r3) : "r"(addr));
}

__device__ __forceinline__ uint32_t pack_h2(float x, float y) {
    __half2 h = __floats2half2_rn(x, y);
    return *reinterpret_cast<uint32_t*>(&h);
}

// Grid barrier: all NBLK CTAs co-resident (1 per SM).
__device__ __forceinline__ void grid_sync_dev() {
    __syncthreads();
    if (threadIdx.x == 0) {
        volatile unsigned* vphs = &g_bar_phs;
        unsigned ph = *vphs;
        __threadfence();
        unsigned ticket = atomicAdd(&g_bar_cnt, 1u);
        if (ticket == NBLK - 1) {
            *((volatile unsigned*)&g_bar_cnt) = 0u;
            __threadfence();
            *vphs = ph + 1u;
        } else {
            while (*vphs == ph) { __nanosleep(32); }
            __threadfence();
        }
    }
    __syncthreads();
}

// ---------------------------------------------------------------------------
// Elementwise fp32 -> fp16 conversion (x4).
// ---------------------------------------------------------------------------
__global__ void cvt_f16_kernel(const float* __restrict__ src, __half* __restrict__ dst, int n4)
{
    int i = blockIdx.x * blockDim.x + threadIdx.x;
    if (i < n4) {
        float4 v = ((const float4*)src)[i];
        ((uint2*)dst)[i] = make_uint2(pack_h2(v.x, v.y), pack_h2(v.z, v.w));
    }
}

// ---------------------------------------------------------------------------
// xproj (fp16): C[m][n] = sum_k A[m][k]*W[n][k] + bias[n]
//   BM=BN=128, BK=32, 256 threads, 8 warps (2m x 4n), warp 64x32.
//   m = t*B + b; A row from cur[(b*T+t)*H]; fp32 global -> fp16 smem -> ldsm.
// ---------------------------------------------------------------------------
#define XROW 40   // halves per smem row (32 + 8 pad) => 80B stride, ldsm conflict-free

__global__ __launch_bounds__(256) void xproj_kernel(
    const float* __restrict__ cur, const float* __restrict__ W,
    const float* __restrict__ bias, float* __restrict__ xp)
{
    __shared__ __half As[2][128 * XROW];   // 10 KB each
    __shared__ __half Bs[2][128 * XROW];

    const int tid  = threadIdx.x;
    const int lane = tid & 31;
    const int wid  = tid >> 5;
    const int wm   = (wid >> 2) * 64;
    const int wn   = (wid & 3) * 32;
    const int m0   = blockIdx.y * 128;
    const int n0   = blockIdx.x * 128;

    // Loaders: per stage (k32) A is 128x32 fp32 = 1024 float4; 4 per thread. B same.
    const float* gpA[4]; const float* gpB[4]; int soff[4];
    #pragma unroll
    for (int i = 0; i < 4; i++) {
        int idx = tid + i * 256;
        int row = idx >> 3, kv = idx & 7;
        int m = m0 + row;
        int b = m & (BB - 1);
        int t = m >> 7;
        gpA[i]  = cur + ((size_t)b * TT + t) * HH + kv * 4;
        gpB[i]  = W + (size_t)(n0 + row) * HH + kv * 4;
        soff[i] = row * XROW + kv * 4;     // halves offset
    }

    float acc[4][4][4];
    #pragma unroll
    for (int a = 0; a < 4; a++)
        #pragma unroll
        for (int b = 0; b < 4; b++)
            #pragma unroll
            for (int c = 0; c < 4; c++) acc[a][b][c] = 0.f;

    float4 ra[4], rb[4];
    #pragma unroll
    for (int i = 0; i < 4; i++) { ra[i] = *(const float4*)gpA[i]; rb[i] = *(const float4*)gpB[i]; }
    #pragma unroll
    for (int i = 0; i < 4; i++) {
        *(uint2*)&As[0][soff[i]] = make_uint2(pack_h2(ra[i].x, ra[i].y), pack_h2(ra[i].z, ra[i].w));
        *(uint2*)&Bs[0][soff[i]] = make_uint2(pack_h2(rb[i].x, rb[i].y), pack_h2(rb[i].z, rb[i].w));
    }
    __syncthreads();

    uint32_t asb[2], bsb[2];
    asb[0] = (uint32_t)__cvta_generic_to_shared(&As[0][0]);
    asb[1] = (uint32_t)__cvta_generic_to_shared(&As[1][0]);
    bsb[0] = (uint32_t)__cvta_generic_to_shared(&Bs[0][0]);
    bsb[1] = (uint32_t)__cvta_generic_to_shared(&Bs[1][0]);

    const int g  = lane >> 3;
    const int r8 = lane & 7;
    const uint32_t aRow = (uint32_t)(((g & 1) * 8 + r8) * 80 + (g >> 1) * 16);
    const uint32_t bRow = (uint32_t)(((g >> 1) * 8 + r8) * 80 + (g & 1) * 16);

    const int NKT = HH / 32;  // 32 stages of k32
    for (int kt = 0; kt < NKT; kt++) {
        int cb = kt & 1;
        if (kt + 1 < NKT) {
            #pragma unroll
            for (int i = 0; i < 4; i++) {
                ra[i] = *(const float4*)(gpA[i] + (kt + 1) * 32);
                rb[i] = *(const float4*)(gpB[i] + (kt + 1) * 32);
            }
        }
        #pragma unroll
        for (int kk = 0; kk < 2; kk++) {
            uint32_t kb = (uint32_t)kk * 32;
            uint32_t af[4][4], bf[2][4];
            #pragma unroll
            for (int mt = 0; mt < 4; mt++)
                ldsm4(af[mt][0], af[mt][1], af[mt][2], af[mt][3],
                      asb[cb] + (uint32_t)(wm + mt * 16) * 80 + aRow + kb);
            #pragma unroll
            for (int nb2 = 0; nb2 < 2; nb2++)
                ldsm4(bf[nb2][0], bf[nb2][1], bf[nb2][2], bf[nb2][3],
                      bsb[cb] + (uint32_t)(wn + nb2 * 16) * 80 + bRow + kb);
            #pragma unroll
            for (int mt = 0; mt < 4; mt++)
                #pragma unroll
                for (int nb2 = 0; nb2 < 2; nb2++) {
                    mma_f16(acc[mt][nb2 * 2],     af[mt], &bf[nb2][0]);
                    mma_f16(acc[mt][nb2 * 2 + 1], af[mt], &bf[nb2][2]);
                }
        }
        if (kt + 1 < NKT) {
            int nb = cb ^ 1;
            #pragma unroll
            for (int i = 0; i < 4; i++) {
                *(uint2*)&As[nb][soff[i]] = make_uint2(pack_h2(ra[i].x, ra[i].y), pack_h2(ra[i].z, ra[i].w));
                *(uint2*)&Bs[nb][soff[i]] = make_uint2(pack_h2(rb[i].x, rb[i].y), pack_h2(rb[i].z, rb[i].w));
            }
            __syncthreads();
        }
    }

    // Epilogue: +bias, coalesced row-major store into xp.
    #pragma unroll
    for (int mt = 0; mt < 4; mt++) {
        int r = m0 + wm + mt * 16 + (lane >> 2);
        #pragma unroll
        for (int nt = 0; nt < 4; nt++) {
            int cg = n0 + wn + nt * 8 + (lane & 3) * 2;
            float2 bz = *(const float2*)(bias + cg);
            float2 v0 = make_float2(acc[mt][nt][0] + bz.x, acc[mt][nt][1] + bz.y);
            float2 v1 = make_float2(acc[mt][nt][2] + bz.x, acc[mt][nt][3] + bz.y);
            *(float2*)(xp + (size_t)r * H3 + cg)       = v0;
            *(float2*)(xp + (size_t)(r + 8) * H3 + cg) = v1;
        }
    }
}

// ---------------------------------------------------------------------------
// Persistent recurrence (fp16): all 128 timesteps of one layer in one launch.
// 128 CTAs (32 o-tiles x 4 b-tiles). CTA tile 32 batch x 96 gates-units.
// 8-stage ring of K32 stages (10 KB each), 2 stages per barrier (16/step).
// ---------------------------------------------------------------------------
#define NST   8
#define SROW  40                   // halves per smem row (32 data + 8 pad) = 80B
#define STGB  (128 * SROW * 2)     // bytes per stage (10240)

__global__ __launch_bounds__(384) void persist_kernel(
    const __half* __restrict__ Wh_h,        // fp16 [3,H,H] (layer slice)
    const float*  __restrict__ bhv,         // [3,H]
    const float*  __restrict__ xp,          // [T,B,3H]
    float*        __restrict__ y,           // [B,T,H]
    float* hA, float* hB, __half* hAh, __half* hBh)
{
    extern __shared__ __half smh[];         // NST * STGB bytes (80 KB)

    const int tid  = threadIdx.x;
    const int lane = tid & 31;
    const int wid  = tid >> 5;              // 0..11
    const int o0   = blockIdx.x * 32;
    const int b0   = blockIdx.y * 32;
    const int wm   = (wid / 6) * 16;        // 0 or 16
    const int wn   = (wid % 6) * 16;        // 0..80

    const uint32_t smbase = (uint32_t)__cvta_generic_to_shared(&smh[0]);

    // cp.async chunk mapping: 512 x 16B chunks per stage (4 per row of 32 halves).
    //   chunks 0..127: h rows 0..31; chunks 128..511: Wh rows 0..95 (gate*32+unit).
    //   tid < 128: chunk tid  + chunk 384+tid ; tid >= 128: chunk tid.
    size_t hOff = 0;
    const __half* wsrc0 = nullptr;
    uint32_t sd0;
    const __half* gs1 = nullptr; uint32_t sd1 = 0;
    {
        if (tid < 128) {
            int row = tid >> 2, kv = tid & 3;
            hOff = (size_t)(b0 + row) * HH + kv * 8;
            sd0  = (uint32_t)(row * 80 + kv * 16);
            int j = tid + 256;              // chunks 384..511 -> Wh rows 64..95
            int wrow = j >> 2, wkv = j & 3;
            gs1 = Wh_h + ((size_t)(wrow >> 5) * HH + o0 + (wrow & 31)) * HH + wkv * 8;
            sd1 = (uint32_t)((32 + wrow) * 80 + wkv * 16);
        } else {
            int j = tid - 128;              // chunks 128..383 -> Wh rows 0..63
            int wrow = j >> 2, wkv = j & 3;
            wsrc0 = Wh_h + ((size_t)(wrow >> 5) * HH + o0 + (wrow & 31)) * HH + wkv * 8;
            sd0   = (uint32_t)((32 + wrow) * 80 + wkv * 16);
        }
    }

    // Invariant ldsm address components (fp16 m16n8k16 canonical mapping).
    const int g  = lane >> 3;
    const int r8 = lane & 7;
    const uint32_t aoff = (uint32_t)((wm + (g & 1) * 8 + r8) * 80 + (g >> 1) * 16);
    const uint32_t boff = (uint32_t)((32 + wn + (g >> 1) * 8 + r8) * 80 + (g & 1) * 16);

    for (int t = 0; t < TT; t++) {
        const __half* hsrc_h = (t & 1) ? hBh : hAh;
        const float*  hprev  = (t & 1) ? hB  : hA;
        float*        hnext  = (t & 1) ? hA  : hB;
        __half*       hnxt_h = (t & 1) ? hAh : hBh;
        const float*  xp_t   = xp + (size_t)t * BB * H3;

        const __half* gs0 = (tid < 128) ? (hsrc_h + hOff) : wsrc0;

        // Prologue: fill stage pairs 0,1,2 (stages 0..5). Stage s covers k=32s.
        #pragma unroll
        for (int p = 0; p < 3; p++) {
            #pragma unroll
            for (int ss = 0; ss < 2; ss++) {
                int s = 2 * p + ss;
                uint32_t sb = smbase + (uint32_t)(s & (NST - 1)) * STGB;
                asm volatile("cp.async.cg.shared.global [%0], [%1], 16;"
                             :: "r"(sb + sd0), "l"(gs0 + s * 32));
                if (tid < 128)
                    asm volatile("cp.async.cg.shared.global [%0], [%1], 16;"
                                 :: "r"(sb + sd1), "l"(gs1 + s * 32));
            }
            asm volatile("cp.async.commit_group;");
        }

        float acc[2][4];
        #pragma unroll
        for (int nt = 0; nt < 2; nt++)
            #pragma unroll
            for (int c = 0; c < 4; c++) acc[nt][c] = 0.f;

        const int NPAIR = HH / 64;  // 16 barrier iterations (2 K32 stages each)
        for (int p = 0; p < NPAIR; p++) {
            asm volatile("cp.async.wait_group 2;");
            __syncthreads();

            if (p < NPAIR - 3) {
                #pragma unroll
                for (int ss = 0; ss < 2; ss++) {
                    int s = 2 * (p + 3) + ss;
                    uint32_t sb = smbase + (uint32_t)(s & (NST - 1)) * STGB;
                    asm volatile("cp.async.cg.shared.global [%0], [%1], 16;"
                                 :: "r"(sb + sd0), "l"(gs0 + s * 32));
                    if (tid < 128)
                        asm volatile("cp.async.cg.shared.global [%0], [%1], 16;"
                                     :: "r"(sb + sd1), "l"(gs1 + s * 32));
                }
            }
            asm volatile("cp.async.commit_group;");

            #pragma unroll
            for (int ss = 0; ss < 2; ss++) {
                uint32_t sb = smbase + (uint32_t)((2 * p + ss) & (NST - 1)) * STGB;
                #pragma unroll
                for (int kk = 0; kk < 2; kk++) {
                    uint32_t kb = (uint32_t)kk * 32;   // k16 = 32 bytes
                    uint32_t af[4], bf[4];
                    ldsm4(af[0], af[1], af[2], af[3], sb + aoff + kb);
                    ldsm4(bf[0], bf[1], bf[2], bf[3], sb + boff + kb);
                    mma_f16(acc[0], af, &bf[0]);
                    mma_f16(acc[1], af, &bf[2]);
                }
            }
        }
        asm volatile("cp.async.wait_group 0;");
        __syncthreads();  // fragment reads done -> safe to alias smem

        // Scatter accumulators: Cs[32][100] fp32 (aliases stage 0-1 region).
        float* Cs = (float*)smh;
        #pragma unroll
        for (int nt = 0; nt < 2; nt++) {
            int r = wm + (lane >> 2);
            int c = wn + nt * 8 + (lane & 3) * 2;
            Cs[r * 100 + c]           = acc[nt][0];
            Cs[r * 100 + c + 1]       = acc[nt][1];
            Cs[(r + 8) * 100 + c]     = acc[nt][2];
            Cs[(r + 8) * 100 + c + 1] = acc[nt][3];
        }
        __syncthreads();

        // Gate fusion: threads 0..255 -> (batch b, 4 consecutive units).
        if (tid < 256) {
            const int b  = tid >> 3;
            const int oq = (tid & 7) * 4;
            const int bg = b0 + b;
            const int og = o0 + oq;
            const float* xpr = xp_t + (size_t)bg * H3;

            float4 xr4 = *(const float4*)(xpr + og);
            float4 xz4 = *(const float4*)(xpr + HH + og);
            float4 xn4 = *(const float4*)(xpr + 2 * HH + og);
            float4 br4 = *(const float4*)(bhv + og);
            float4 bz4 = *(const float4*)(bhv + HH + og);
            float4 bn4 = *(const float4*)(bhv + 2 * HH + og);
            float4 hp4 = *(const float4*)(hprev + (size_t)bg * HH + og);

            float hv[4];
            #pragma unroll
            for (int j = 0; j < 4; j++) {
                int o = oq + j;
                float hr = Cs[b * 100 + o]      + ((const float*)&br4)[j];
                float hz = Cs[b * 100 + 32 + o] + ((const float*)&bz4)[j];
                float hn = Cs[b * 100 + 64 + o] + ((const float*)&bn4)[j];
                float r  = 1.f / (1.f + __expf(-(((const float*)&xr4)[j] + hr)));
                float z  = 1.f / (1.f + __expf(-(((const float*)&xz4)[j] + hz)));
                float n  = tanhf(((const float*)&xn4)[j] + r * hn);
                hv[j] = (1.f - z) * n + z * ((const float*)&hp4)[j];
            }
            *(float4*)(hnext + (size_t)bg * HH + og) = make_float4(hv[0], hv[1], hv[2], hv[3]);
            *(float4*)(y + ((size_t)bg * TT + t) * HH + og) = make_float4(hv[0], hv[1], hv[2], hv[3]);
            *(uint2*)(hnxt_h + (size_t)bg * HH + og) =
                make_uint2(pack_h2(hv[0], hv[1]), pack_h2(hv[2], hv[3]));
        }

        if (t + 1 < TT) grid_sync_dev();
    }
}

// ---------------------------------------------------------------------------
extern "C" void kernel_launch(void* const* d_in, const int* in_sizes, int n_in,
                              void* d_out, int out_size)
{
    (void)in_sizes; (void)n_in; (void)out_size;
    const float* x   = (const float*)d_in[0];  // [B,T,H]
    const float* h0  = (const float*)d_in[1];  // [L,B,H]
    const float* Wx  = (const float*)d_in[2];  // [L,3,H,H]
    const float* Wh  = (const float*)d_in[3];  // [L,3,H,H]
    const float* bx  = (const float*)d_in[4];  // [L,3,H]
    const float* bh  = (const float*)d_in[5];  // [L,3,H]
    float* out   = (float*)d_out;              // [B,T,H] then [L,B,H]
    float* hlast = out + (size_t)BB * TT * HH;

    float*  xp   = nullptr;
    float*  hbuf = nullptr;
    __half* whh  = nullptr;
    __half* hh   = nullptr;
    cudaGetSymbolAddress((void**)&xp,   g_xp);
    cudaGetSymbolAddress((void**)&hbuf, g_hbuf);
    cudaGetSymbolAddress((void**)&whh,  g_whh);
    cudaGetSymbolAddress((void**)&hh,   g_hh);
    float*  hA  = hbuf;
    float*  hB  = hbuf + BB * HH;
    __half* hAh = hh;
    __half* hBh = hh + BB * HH;

    cudaFuncSetAttribute(persist_kernel,
                         cudaFuncAttributeMaxDynamicSharedMemorySize, NST * STGB);

    // Pre-convert Wh (both layers) to fp16.
    {
        int n4 = 2 * 3 * HH * HH / 4;
        cvt_f16_kernel<<<n4 / 256, 256>>>(Wh, whh, n4);
    }

    dim3 xgrid(H3 / 128, (BB * TT) / 128);  // (24, 128)
    dim3 pgrid(HH / 32, BB / 32);           // (32, 4) = 128 CTAs, all resident

    for (int l = 0; l < 2; l++) {
        const float* cur = (l == 0) ? x : out;  // layer-1 input = layer-0 output
        xproj_kernel<<<xgrid, 256>>>(cur, Wx + (size_t)l * 3 * HH * HH,
                                     bx + (size_t)l * 3 * HH, xp);
        cudaMemcpyAsync(hA, h0 + (size_t)l * BB * HH, (size_t)BB * HH * sizeof(float),
                        cudaMemcpyDeviceToDevice);
        {
            int n4 = BB * HH / 4;
            cvt_f16_kernel<<<n4 / 256, 256>>>(h0 + (size_t)l * BB * HH, hAh, n4);
        }
        persist_kernel<<<pgrid, 384, NST * STGB>>>(
            whh + (size_t)l * 3 * HH * HH, bh + (size_t)l * 3 * HH,
            xp, out, hA, hB, hAh, hBh);
        // T=128 even -> final hidden ends up in hA
        cudaMemcpyAsync(hlast + (size_t)l * BB * HH, hA, (size_t)BB * HH * sizeof(float),
                        cudaMemcpyDeviceToDevice);
    }
}

// round 7
// speedup vs baseline: 1.9348x; 1.1022x over previous
#include <cuda_runtime.h>
#include <cuda_fp16.h>
#include <cstdint>
#include <cstddef>

#define BB 128
#define TT 128
#define HH 1024
#define H3 3072
#define NBLK 128   // persistent grid (64 o-tiles x 2 b-tiles), all resident

// Scratch (static device globals -- no dynamic allocation allowed).
__device__ float  g_xp[50331648ULL];          // [T][B][3H] fp32 (192 MB)
__device__ __half g_whh[2ULL * 3 * HH * HH];  // Wh fp16 (12.6 MB)
__device__ float  g_hbuf[2 * BB * HH];        // double-buffered h (fp32 carrier)
__device__ __half g_hh[2 * BB * HH];          // double-buffered h (fp16 operand)
__device__ float  g_bias[2 * H3];             // xproj bias: bx+bh (r,z), bx (n)
__device__ unsigned g_bar_cnt;
__device__ unsigned g_bar_phs;

__device__ __forceinline__ uint32_t pack_h2(float x, float y) {
    __half2 h = __floats2half2_rn(x, y);
    return *reinterpret_cast<uint32_t*>(&h);
}

__device__ __forceinline__ void mma_f16(float d[4], const uint32_t a[4], const uint32_t b[2]) {
    asm volatile(
        "mma.sync.aligned.m16n8k16.row.col.f32.f16.f16.f32 "
        "{%0,%1,%2,%3}, {%4,%5,%6,%7}, {%8,%9}, {%0,%1,%2,%3};"
        : "+f"(d[0]), "+f"(d[1]), "+f"(d[2]), "+f"(d[3])
        : "r"(a[0]), "r"(a[1]), "r"(a[2]), "r"(a[3]), "r"(b[0]), "r"(b[1]));
}

__device__ __forceinline__ void ldsm4(uint32_t& r0, uint32_t& r1, uint32_t& r2, uint32_t& r3,
                                      uint32_t addr) {
    asm volatile("ldmatrix.sync.aligned.m8n8.x4.shared.b16 {%0,%1,%2,%3}, [%4];"
                 : "=r"(r0), "=r"(r1), "=r"(r2), "=r"(r3) : "r"(addr));
}

// Grid barrier: all NBLK CTAs co-resident (1 per SM).
__device__ __forceinline__ void grid_sync_dev() {
    __syncthreads();
    if (threadIdx.x == 0) {
        volatile unsigned* vphs = &g_bar_phs;
        unsigned ph = *vphs;
        __threadfence();
        unsigned ticket = atomicAdd(&g_bar_cnt, 1u);
        if (ticket == NBLK - 1) {
            *((volatile unsigned*)&g_bar_cnt) = 0u;
            __threadfence();
            *vphs = ph + 1u;
        } else {
            while (*vphs == ph) { __nanosleep(32); }
            __threadfence();
        }
    }
    __syncthreads();
}

// ---------------------------------------------------------------------------
__global__ void cvt_f16_kernel(const float* __restrict__ src, __half* __restrict__ dst, int n4)
{
    int i = blockIdx.x * blockDim.x + threadIdx.x;
    if (i < n4) {
        float4 v = ((const float4*)src)[i];
        ((uint2*)dst)[i] = make_uint2(pack_h2(v.x, v.y), pack_h2(v.z, v.w));
    }
}

// Combined bias for xproj: bx + bh for gates r,z ; bx only for gate n.
__global__ void bias_kernel(const float* __restrict__ bx, const float* __restrict__ bh,
                            float* __restrict__ out)
{
    int i = blockIdx.x * blockDim.x + threadIdx.x;
    if (i < 2 * H3) {
        int n = i % H3;
        float v = bx[i];
        if (n < 2 * HH) v += bh[i];
        out[i] = v;
    }
}

// ---------------------------------------------------------------------------
// xproj (fp16): C[m][n] = sum_k A[m][k]*W[n][k] + bias[n]   (validated in R5)
// ---------------------------------------------------------------------------
#define XROW 40

__global__ __launch_bounds__(256) void xproj_kernel(
    const float* __restrict__ cur, const float* __restrict__ W,
    const float* __restrict__ bias, float* __restrict__ xp)
{
    __shared__ __half As[2][128 * XROW];
    __shared__ __half Bs[2][128 * XROW];

    const int tid  = threadIdx.x;
    const int lane = tid & 31;
    const int wid  = tid >> 5;
    const int wm   = (wid >> 2) * 64;
    const int wn   = (wid & 3) * 32;
    const int m0   = blockIdx.y * 128;
    const int n0   = blockIdx.x * 128;

    const float* gpA[4]; const float* gpB[4]; int soff[4];
    #pragma unroll
    for (int i = 0; i < 4; i++) {
        int idx = tid + i * 256;
        int row = idx >> 3, kv = idx & 7;
        int m = m0 + row;
        int b = m & (BB - 1);
        int t = m >> 7;
        gpA[i]  = cur + ((size_t)b * TT + t) * HH + kv * 4;
        gpB[i]  = W + (size_t)(n0 + row) * HH + kv * 4;
        soff[i] = row * XROW + kv * 4;
    }

    float acc[4][4][4];
    #pragma unroll
    for (int a = 0; a < 4; a++)
        #pragma unroll
        for (int b = 0; b < 4; b++)
            #pragma unroll
            for (int c = 0; c < 4; c++) acc[a][b][c] = 0.f;

    float4 ra[4], rb[4];
    #pragma unroll
    for (int i = 0; i < 4; i++) { ra[i] = *(const float4*)gpA[i]; rb[i] = *(const float4*)gpB[i]; }
    #pragma unroll
    for (int i = 0; i < 4; i++) {
        *(uint2*)&As[0][soff[i]] = make_uint2(pack_h2(ra[i].x, ra[i].y), pack_h2(ra[i].z, ra[i].w));
        *(uint2*)&Bs[0][soff[i]] = make_uint2(pack_h2(rb[i].x, rb[i].y), pack_h2(rb[i].z, rb[i].w));
    }
    __syncthreads();

    uint32_t asb[2], bsb[2];
    asb[0] = (uint32_t)__cvta_generic_to_shared(&As[0][0]);
    asb[1] = (uint32_t)__cvta_generic_to_shared(&As[1][0]);
    bsb[0] = (uint32_t)__cvta_generic_to_shared(&Bs[0][0]);
    bsb[1] = (uint32_t)__cvta_generic_to_shared(&Bs[1][0]);

    const int g  = lane >> 3;
    const int r8 = lane & 7;
    const uint32_t aRow = (uint32_t)(((g & 1) * 8 + r8) * 80 + (g >> 1) * 16);
    const uint32_t bRow = (uint32_t)(((g >> 1) * 8 + r8) * 80 + (g & 1) * 16);

    const int NKT = HH / 32;
    for (int kt = 0; kt < NKT; kt++) {
        int cb = kt & 1;
        if (kt + 1 < NKT) {
            #pragma unroll
            for (int i = 0; i < 4; i++) {
                ra[i] = *(const float4*)(gpA[i] + (kt + 1) * 32);
                rb[i] = *(const float4*)(gpB[i] + (kt + 1) * 32);
            }
        }
        #pragma unroll
        for (int kk = 0; kk < 2; kk++) {
            uint32_t kb = (uint32_t)kk * 32;
            uint32_t af[4][4], bf[2][4];
            #pragma unroll
            for (int mt = 0; mt < 4; mt++)
                ldsm4(af[mt][0], af[mt][1], af[mt][2], af[mt][3],
                      asb[cb] + (uint32_t)(wm + mt * 16) * 80 + aRow + kb);
            #pragma unroll
            for (int nb2 = 0; nb2 < 2; nb2++)
                ldsm4(bf[nb2][0], bf[nb2][1], bf[nb2][2], bf[nb2][3],
                      bsb[cb] + (uint32_t)(wn + nb2 * 16) * 80 + bRow + kb);
            #pragma unroll
            for (int mt = 0; mt < 4; mt++)
                #pragma unroll
                for (int nb2 = 0; nb2 < 2; nb2++) {
                    mma_f16(acc[mt][nb2 * 2],     af[mt], &bf[nb2][0]);
                    mma_f16(acc[mt][nb2 * 2 + 1], af[mt], &bf[nb2][2]);
                }
        }
        if (kt + 1 < NKT) {
            int nb = cb ^ 1;
            #pragma unroll
            for (int i = 0; i < 4; i++) {
                *(uint2*)&As[nb][soff[i]] = make_uint2(pack_h2(ra[i].x, ra[i].y), pack_h2(ra[i].z, ra[i].w));
                *(uint2*)&Bs[nb][soff[i]] = make_uint2(pack_h2(rb[i].x, rb[i].y), pack_h2(rb[i].z, rb[i].w));
            }
            __syncthreads();
        }
    }

    #pragma unroll
    for (int mt = 0; mt < 4; mt++) {
        int r = m0 + wm + mt * 16 + (lane >> 2);
        #pragma unroll
        for (int nt = 0; nt < 4; nt++) {
            int cg = n0 + wn + nt * 8 + (lane & 3) * 2;
            float2 bz = *(const float2*)(bias + cg);
            float2 v0 = make_float2(acc[mt][nt][0] + bz.x, acc[mt][nt][1] + bz.y);
            float2 v1 = make_float2(acc[mt][nt][2] + bz.x, acc[mt][nt][3] + bz.y);
            *(float2*)(xp + (size_t)r * H3 + cg)       = v0;
            *(float2*)(xp + (size_t)(r + 8) * H3 + cg) = v1;
        }
    }
}

// ---------------------------------------------------------------------------
// Persistent recurrence, Wh fully SMEM-resident.
//   CTA: 64 batches x 16 units (48 B-rows = unit*3+gate). Grid (64,2)=128.
//   Wh: 48x1024 f16 (96 KB) loaded once; h: 64x1024 f16 (128 KB) per step.
//   Row stride 2048B with per-row chunk swizzle (c ^= row&7) -> no padding,
//   conflict-free cp.async writes and ldmatrix reads. Mainloop barrier-free.
// ---------------------------------------------------------------------------
#define WOFF 1024
#define HOFF (WOFF + 48 * 2048)          // 99328
#define SMEM_TOT (HOFF + 64 * 2048)      // 230400

__global__ __launch_bounds__(384) void persist_kernel(
    const __half* __restrict__ Wh_h,     // fp16 [3,H,H] (layer slice)
    const float*  __restrict__ bhn,      // [H] gate-n hidden bias
    const float*  __restrict__ xp,       // [T,B,3H]
    float*        __restrict__ y,        // [B,T,H]
    float* hA, float* hB, __half* hAh, __half* hBh)
{
    extern __shared__ uint8_t dsm[];
    const uint32_t smbase = (uint32_t)__cvta_generic_to_shared(dsm);
    const int tid  = threadIdx.x;
    const int lane = tid & 31;
    const int wid  = tid >> 5;           // 0..11
    const int o0   = blockIdx.x * 16;    // unit base
    const int b0   = blockIdx.y * 64;    // batch base
    const int wm   = (wid / 3) * 16;     // 0,16,32,48
    const int wn   = (wid % 3) * 16;     // 0,16,32

    // Header: bh_n for this CTA's 16 units.
    if (tid < 16) ((float*)dsm)[tid] = bhn[o0 + tid];

    // One-time Wh load: 48 rows x 128 chunks(16B). Row r = 3*u + g.
    for (int i = tid; i < 6144; i += 384) {
        int r = i >> 7, c = i & 127;
        int u = r / 3, g = r - 3 * u;
        const __half* src = Wh_h + ((size_t)(g * HH + o0 + u)) * HH + c * 8;
        uint32_t dst = smbase + WOFF + (uint32_t)r * 2048 + (uint32_t)((c ^ (r & 7)) << 4);
        asm volatile("cp.async.cg.shared.global [%0], [%1], 16;" :: "r"(dst), "l"(src));
    }
    asm volatile("cp.async.commit_group;");
    asm volatile("cp.async.wait_group 0;");
    __syncthreads();

    // Invariant ldsm per-lane bases (chunk index XORed per iteration).
    const int g  = lane >> 3;
    const int r8 = lane & 7;
    const int arow = wm + (g & 1) * 8 + r8;          // h row (batch)
    const int brow = wn + (g >> 1) * 8 + r8;         // Wh row
    const uint32_t aBase = smbase + HOFF + (uint32_t)arow * 2048;
    const uint32_t bBase = smbase + WOFF + (uint32_t)brow * 2048;
    const uint32_t arm = (uint32_t)(arow & 7);
    const uint32_t brm = (uint32_t)(brow & 7);
    const uint32_t ahalf = (uint32_t)(g >> 1);       // k-half for A
    const uint32_t bhalf = (uint32_t)(g & 1);        // k-half for B

    for (int t = 0; t < TT; t++) {
        const __half* hsrc  = (t & 1) ? hBh : hAh;
        const float*  hprev = (t & 1) ? hB  : hA;
        float*        hnext = (t & 1) ? hA  : hB;
        __half*       hnh   = (t & 1) ? hAh : hBh;
        const float*  xp_t  = xp + (size_t)t * BB * H3;

        // Issue the step's h tile as 4 commit groups (each 64 rows x 32 chunks).
        #pragma unroll 1
        for (int p = 0; p < 4; p++) {
            for (int i = tid; i < 2048; i += 384) {
                int row = i >> 5;
                int c   = (p << 5) + (i & 31);
                const __half* src = hsrc + (size_t)(b0 + row) * HH + c * 8;
                uint32_t dst = smbase + HOFF + (uint32_t)row * 2048
                             + (uint32_t)((c ^ (row & 7)) << 4);
                asm volatile("cp.async.cg.shared.global [%0], [%1], 16;" :: "r"(dst), "l"(src));
            }
            asm volatile("cp.async.commit_group;");
        }

        float acc[2][4];
        #pragma unroll
        for (int nt = 0; nt < 2; nt++)
            #pragma unroll
            for (int c = 0; c < 4; c++) acc[nt][c] = 0.f;

        // Mainloop: 4 phases x 16 K16, barrier-free inside each phase.
        #pragma unroll 1
        for (int p = 0; p < 4; p++) {
            if      (p == 0) asm volatile("cp.async.wait_group 3;");
            else if (p == 1) asm volatile("cp.async.wait_group 2;");
            else if (p == 2) asm volatile("cp.async.wait_group 1;");
            else             asm volatile("cp.async.wait_group 0;");
            __syncthreads();

            const int kt0 = p * 16;
            #pragma unroll
            for (int kk = 0; kk < 16; kk++) {
                uint32_t kt = (uint32_t)(kt0 + kk);
                uint32_t af[4], bf[4];
                uint32_t ca = 2 * kt + ahalf;
                uint32_t cbk = 2 * kt + bhalf;
                ldsm4(af[0], af[1], af[2], af[3], aBase + ((ca ^ arm) << 4));
                ldsm4(bf[0], bf[1], bf[2], bf[3], bBase + ((cbk ^ brm) << 4));
                mma_f16(acc[0], af, &bf[0]);
                mma_f16(acc[1], af, &bf[2]);
            }
        }
        __syncthreads();   // all fragment reads done -> safe to alias h region

        // Scatter accumulators: Cs[64][52] fp32, aliased onto h region.
        float* Cs = (float*)(dsm + HOFF);
        #pragma unroll
        for (int nt = 0; nt < 2; nt++) {
            int r = wm + (lane >> 2);
            int c = wn + nt * 8 + (lane & 3) * 2;
            Cs[r * 52 + c]           = acc[nt][0];
            Cs[r * 52 + c + 1]       = acc[nt][1];
            Cs[(r + 8) * 52 + c]     = acc[nt][2];
            Cs[(r + 8) * 52 + c + 1] = acc[nt][3];
        }
        __syncthreads();

        // Gate fusion: threads 0..255 -> (batch b = tid>>2, 4 units).
        if (tid < 256) {
            const int b  = tid >> 2;
            const int u0 = (tid & 3) * 4;
            const int bg = b0 + b;
            const int og = o0 + u0;
            const float* xpr = xp_t + (size_t)bg * H3 + og;
            const float* bhn_s = (const float*)dsm;

            float4 xr4 = *(const float4*)(xpr);
            float4 xz4 = *(const float4*)(xpr + HH);
            float4 xn4 = *(const float4*)(xpr + 2 * HH);
            float4 hp4 = *(const float4*)(hprev + (size_t)bg * HH + og);

            float hv[4];
            #pragma unroll
            for (int j = 0; j < 4; j++) {
                int u = u0 + j;
                float hr = Cs[b * 52 + 3 * u + 0];
                float hz = Cs[b * 52 + 3 * u + 1];
                float hn = Cs[b * 52 + 3 * u + 2] + bhn_s[u];
                float r  = 1.f / (1.f + __expf(-(((const float*)&xr4)[j] + hr)));
                float z  = 1.f / (1.f + __expf(-(((const float*)&xz4)[j] + hz)));
                float n  = tanhf(((const float*)&xn4)[j] + r * hn);
                hv[j] = (1.f - z) * n + z * ((const float*)&hp4)[j];
            }
            *(float4*)(hnext + (size_t)bg * HH + og) = make_float4(hv[0], hv[1], hv[2], hv[3]);
            *(float4*)(y + ((size_t)bg * TT + t) * HH + og) = make_float4(hv[0], hv[1], hv[2], hv[3]);
            *(uint2*)(hnh + (size_t)bg * HH + og) =
                make_uint2(pack_h2(hv[0], hv[1]), pack_h2(hv[2], hv[3]));
        }

        if (t + 1 < TT) grid_sync_dev();
    }
}

// ---------------------------------------------------------------------------
extern "C" void kernel_launch(void* const* d_in, const int* in_sizes, int n_in,
                              void* d_out, int out_size)
{
    (void)in_sizes; (void)n_in; (void)out_size;
    const float* x   = (const float*)d_in[0];  // [B,T,H]
    const float* h0  = (const float*)d_in[1];  // [L,B,H]
    const float* Wx  = (const float*)d_in[2];  // [L,3,H,H]
    const float* Wh  = (const float*)d_in[3];  // [L,3,H,H]
    const float* bx  = (const float*)d_in[4];  // [L,3,H]
    const float* bh  = (const float*)d_in[5];  // [L,3,H]
    float* out   = (float*)d_out;              // [B,T,H] then [L,B,H]
    float* hlast = out + (size_t)BB * TT * HH;

    float*  xp   = nullptr;
    float*  hbuf = nullptr;
    __half* whh  = nullptr;
    __half* hh   = nullptr;
    float*  gb   = nullptr;
    cudaGetSymbolAddress((void**)&xp,   g_xp);
    cudaGetSymbolAddress((void**)&hbuf, g_hbuf);
    cudaGetSymbolAddress((void**)&whh,  g_whh);
    cudaGetSymbolAddress((void**)&hh,   g_hh);
    cudaGetSymbolAddress((void**)&gb,   g_bias);
    float*  hA  = hbuf;
    float*  hB  = hbuf + BB * HH;
    __half* hAh = hh;
    __half* hBh = hh + BB * HH;

    cudaFuncSetAttribute(persist_kernel,
                         cudaFuncAttributeMaxDynamicSharedMemorySize, SMEM_TOT);

    // Pre-convert Wh to fp16; build combined xproj bias.
    {
        int n4 = 2 * 3 * HH * HH / 4;
        cvt_f16_kernel<<<n4 / 256, 256>>>(Wh, whh, n4);
        bias_kernel<<<(2 * H3 + 255) / 256, 256>>>(bx, bh, gb);
    }

    dim3 xgrid(H3 / 128, (BB * TT) / 128);  // (24, 128)
    dim3 pgrid(64, 2);                      // 128 CTAs

    for (int l = 0; l < 2; l++) {
        const float* cur = (l == 0) ? x : out;  // layer-1 input = layer-0 output
        xproj_kernel<<<xgrid, 256>>>(cur, Wx + (size_t)l * 3 * HH * HH,
                                     gb + (size_t)l * H3, xp);
        cudaMemcpyAsync(hA, h0 + (size_t)l * BB * HH, (size_t)BB * HH * sizeof(float),
                        cudaMemcpyDeviceToDevice);
        {
            int n4 = BB * HH / 4;
            cvt_f16_kernel<<<n4 / 256, 256>>>(h0 + (size_t)l * BB * HH, hAh, n4);
        }
        persist_kernel<<<pgrid, 384, SMEM_TOT>>>(
            whh + (size_t)l * 3 * HH * HH,
            bh + (size_t)l * H3 + 2 * HH,     // bh_n
            xp, out, hA, hB, hAh, hBh);
        // T=128 even -> final hidden ends up in hA
        cudaMemcpyAsync(hlast + (size_t)l * BB * HH, hA, (size_t)BB * HH * sizeof(float),
                        cudaMemcpyDeviceToDevice);
    }
}

// round 8
// speedup vs baseline: 2.0875x; 1.0789x over previous
#include <cuda_runtime.h>
#include <cuda_fp16.h>
#include <cstdint>
#include <cstddef>

#define BB 128
#define TT 128
#define HH 1024
#define H3 3072
#define NBLK 128   // persistent grid (64 o-tiles x 2 b-tiles), all resident

// Scratch (static device globals -- no dynamic allocation allowed).
__device__ float  g_xp[50331648ULL];          // [T][B][3H] fp32 (192 MB)
__device__ __half g_whh[2ULL * 3 * HH * HH];  // Wh fp16 (12.6 MB)
__device__ __half g_hh[2 * BB * HH];          // double-buffered h (fp16 operand)
__device__ float  g_bias[2 * H3];             // xproj bias: bx+bh (r,z), bx (n)
__device__ unsigned g_bar_cnt;
__device__ unsigned g_bar_phs;

__device__ __forceinline__ uint32_t pack_h2(float x, float y) {
    __half2 h = __floats2half2_rn(x, y);
    return *reinterpret_cast<uint32_t*>(&h);
}

__device__ __forceinline__ void mma_f16(float d[4], const uint32_t a[4], const uint32_t b[2]) {
    asm volatile(
        "mma.sync.aligned.m16n8k16.row.col.f32.f16.f16.f32 "
        "{%0,%1,%2,%3}, {%4,%5,%6,%7}, {%8,%9}, {%0,%1,%2,%3};"
        : "+f"(d[0]), "+f"(d[1]), "+f"(d[2]), "+f"(d[3])
        : "r"(a[0]), "r"(a[1]), "r"(a[2]), "r"(a[3]), "r"(b[0]), "r"(b[1]));
}

__device__ __forceinline__ void ldsm4(uint32_t& r0, uint32_t& r1, uint32_t& r2, uint32_t& r3,
                                      uint32_t addr) {
    asm volatile("ldmatrix.sync.aligned.m8n8.x4.shared.b16 {%0,%1,%2,%3}, [%4];"
                 : "=r"(r0), "=r"(r1), "=r"(r2), "=r"(r3) : "r"(addr));
}

// Grid barrier: all NBLK CTAs co-resident (1 per SM). Tight spin, no nanosleep.
__device__ __forceinline__ void grid_sync_dev() {
    __syncthreads();
    if (threadIdx.x == 0) {
        volatile unsigned* vphs = &g_bar_phs;
        unsigned ph = *vphs;
        __threadfence();
        unsigned ticket = atomicAdd(&g_bar_cnt, 1u);
        if (ticket == NBLK - 1) {
            *((volatile unsigned*)&g_bar_cnt) = 0u;
            __threadfence();
            *vphs = ph + 1u;
        } else {
            while (*vphs == ph) {}
            __threadfence();
        }
    }
    __syncthreads();
}

// ---------------------------------------------------------------------------
__global__ void cvt_f16_kernel(const float* __restrict__ src, __half* __restrict__ dst, int n4)
{
    int i = blockIdx.x * blockDim.x + threadIdx.x;
    if (i < n4) {
        float4 v = ((const float4*)src)[i];
        ((uint2*)dst)[i] = make_uint2(pack_h2(v.x, v.y), pack_h2(v.z, v.w));
    }
}

// Combined bias for xproj: bx + bh for gates r,z ; bx only for gate n.
__global__ void bias_kernel(const float* __restrict__ bx, const float* __restrict__ bh,
                            float* __restrict__ out)
{
    int i = blockIdx.x * blockDim.x + threadIdx.x;
    if (i < 2 * H3) {
        int n = i % H3;
        float v = bx[i];
        if (n < 2 * HH) v += bh[i];
        out[i] = v;
    }
}

// ---------------------------------------------------------------------------
// xproj (fp16): C[m][n] = sum_k A[m][k]*W[n][k] + bias[n]   (validated)
// ---------------------------------------------------------------------------
#define XROW 40

__global__ __launch_bounds__(256) void xproj_kernel(
    const float* __restrict__ cur, const float* __restrict__ W,
    const float* __restrict__ bias, float* __restrict__ xp)
{
    __shared__ __half As[2][128 * XROW];
    __shared__ __half Bs[2][128 * XROW];

    const int tid  = threadIdx.x;
    const int lane = tid & 31;
    const int wid  = tid >> 5;
    const int wm   = (wid >> 2) * 64;
    const int wn   = (wid & 3) * 32;
    const int m0   = blockIdx.y * 128;
    const int n0   = blockIdx.x * 128;

    const float* gpA[4]; const float* gpB[4]; int soff[4];
    #pragma unroll
    for (int i = 0; i < 4; i++) {
        int idx = tid + i * 256;
        int row = idx >> 3, kv = idx & 7;
        int m = m0 + row;
        int b = m & (BB - 1);
        int t = m >> 7;
        gpA[i]  = cur + ((size_t)b * TT + t) * HH + kv * 4;
        gpB[i]  = W + (size_t)(n0 + row) * HH + kv * 4;
        soff[i] = row * XROW + kv * 4;
    }

    float acc[4][4][4];
    #pragma unroll
    for (int a = 0; a < 4; a++)
        #pragma unroll
        for (int b = 0; b < 4; b++)
            #pragma unroll
            for (int c = 0; c < 4; c++) acc[a][b][c] = 0.f;

    float4 ra[4], rb[4];
    #pragma unroll
    for (int i = 0; i < 4; i++) { ra[i] = *(const float4*)gpA[i]; rb[i] = *(const float4*)gpB[i]; }
    #pragma unroll
    for (int i = 0; i < 4; i++) {
        *(uint2*)&As[0][soff[i]] = make_uint2(pack_h2(ra[i].x, ra[i].y), pack_h2(ra[i].z, ra[i].w));
        *(uint2*)&Bs[0][soff[i]] = make_uint2(pack_h2(rb[i].x, rb[i].y), pack_h2(rb[i].z, rb[i].w));
    }
    __syncthreads();

    uint32_t asb[2], bsb[2];
    asb[0] = (uint32_t)__cvta_generic_to_shared(&As[0][0]);
    asb[1] = (uint32_t)__cvta_generic_to_shared(&As[1][0]);
    bsb[0] = (uint32_t)__cvta_generic_to_shared(&Bs[0][0]);
    bsb[1] = (uint32_t)__cvta_generic_to_shared(&Bs[1][0]);

    const int g  = lane >> 3;
    const int r8 = lane & 7;
    const uint32_t aRow = (uint32_t)(((g & 1) * 8 + r8) * 80 + (g >> 1) * 16);
    const uint32_t bRow = (uint32_t)(((g >> 1) * 8 + r8) * 80 + (g & 1) * 16);

    const int NKT = HH / 32;
    for (int kt = 0; kt < NKT; kt++) {
        int cb = kt & 1;
        if (kt + 1 < NKT) {
            #pragma unroll
            for (int i = 0; i < 4; i++) {
                ra[i] = *(const float4*)(gpA[i] + (kt + 1) * 32);
                rb[i] = *(const float4*)(gpB[i] + (kt + 1) * 32);
            }
        }
        #pragma unroll
        for (int kk = 0; kk < 2; kk++) {
            uint32_t kb = (uint32_t)kk * 32;
            uint32_t af[4][4], bf[2][4];
            #pragma unroll
            for (int mt = 0; mt < 4; mt++)
                ldsm4(af[mt][0], af[mt][1], af[mt][2], af[mt][3],
                      asb[cb] + (uint32_t)(wm + mt * 16) * 80 + aRow + kb);
            #pragma unroll
            for (int nb2 = 0; nb2 < 2; nb2++)
                ldsm4(bf[nb2][0], bf[nb2][1], bf[nb2][2], bf[nb2][3],
                      bsb[cb] + (uint32_t)(wn + nb2 * 16) * 80 + bRow + kb);
            #pragma unroll
            for (int mt = 0; mt < 4; mt++)
                #pragma unroll
                for (int nb2 = 0; nb2 < 2; nb2++) {
                    mma_f16(acc[mt][nb2 * 2],     af[mt], &bf[nb2][0]);
                    mma_f16(acc[mt][nb2 * 2 + 1], af[mt], &bf[nb2][2]);
                }
        }
        if (kt + 1 < NKT) {
            int nb = cb ^ 1;
            #pragma unroll
            for (int i = 0; i < 4; i++) {
                *(uint2*)&As[nb][soff[i]] = make_uint2(pack_h2(ra[i].x, ra[i].y), pack_h2(ra[i].z, ra[i].w));
                *(uint2*)&Bs[nb][soff[i]] = make_uint2(pack_h2(rb[i].x, rb[i].y), pack_h2(rb[i].z, rb[i].w));
            }
            __syncthreads();
        }
    }

    #pragma unroll
    for (int mt = 0; mt < 4; mt++) {
        int r = m0 + wm + mt * 16 + (lane >> 2);
        #pragma unroll
        for (int nt = 0; nt < 4; nt++) {
            int cg = n0 + wn + nt * 8 + (lane & 3) * 2;
            float2 bz = *(const float2*)(bias + cg);
            float2 v0 = make_float2(acc[mt][nt][0] + bz.x, acc[mt][nt][1] + bz.y);
            float2 v1 = make_float2(acc[mt][nt][2] + bz.x, acc[mt][nt][3] + bz.y);
            *(float2*)(xp + (size_t)r * H3 + cg)       = v0;
            *(float2*)(xp + (size_t)(r + 8) * H3 + cg) = v1;
        }
    }
}

// ---------------------------------------------------------------------------
// Persistent recurrence v2: Wh SMEM-resident, h carried in registers,
// xp prefetched ahead of the GEMM, 2-phase h streaming, tight grid barrier.
//   CTA: 64 batches x 16 units (48 B-rows = unit*3+gate). Grid (64,2)=128.
// ---------------------------------------------------------------------------
#define WOFF 1024
#define HOFF (WOFF + 48 * 2048)          // 99328
#define SMEM_TOT (HOFF + 64 * 2048)      // 230400

__global__ __launch_bounds__(384) void persist_kernel(
    const __half* __restrict__ Wh_h,     // fp16 [3,H,H] (layer slice)
    const float*  __restrict__ bhn,      // [H] gate-n hidden bias
    const float*  __restrict__ h0l,      // fp32 [B,H] initial hidden (layer slice)
    const float*  __restrict__ xp,       // [T,B,3H]
    float*        __restrict__ y,        // [B,T,H]
    float*        __restrict__ hlast,    // fp32 [B,H] final hidden out
    __half* hAh, __half* hBh)
{
    extern __shared__ uint8_t dsm[];
    const uint32_t smbase = (uint32_t)__cvta_generic_to_shared(dsm);
    const int tid  = threadIdx.x;
    const int lane = tid & 31;
    const int wid  = tid >> 5;           // 0..11
    const int o0   = blockIdx.x * 16;    // unit base
    const int b0   = blockIdx.y * 64;    // batch base
    const int wm   = (wid / 3) * 16;     // 0,16,32,48
    const int wn   = (wid % 3) * 16;     // 0,16,32

    // Header: bh_n for this CTA's 16 units.
    if (tid < 16) ((float*)dsm)[tid] = bhn[o0 + tid];

    // One-time Wh load: 48 rows x 128 chunks(16B). Row r = 3*u + g.
    for (int i = tid; i < 6144; i += 384) {
        int r = i >> 7, c = i & 127;
        int u = r / 3, g = r - 3 * u;
        const __half* src = Wh_h + ((size_t)(g * HH + o0 + u)) * HH + c * 8;
        uint32_t dst = smbase + WOFF + (uint32_t)r * 2048 + (uint32_t)((c ^ (r & 7)) << 4);
        asm volatile("cp.async.cg.shared.global [%0], [%1], 16;" :: "r"(dst), "l"(src));
    }
    asm volatile("cp.async.commit_group;");

    // Epilogue thread mapping (fixed across steps): b = tid>>2, u0 = (tid&3)*4.
    const int eb  = tid >> 2;
    const int eu0 = (tid & 3) * 4;
    const int ebg = b0 + eb;
    const int eog = o0 + eu0;

    // h carried in registers; init from h0 (fp32, exact).
    float hv[4] = {0.f, 0.f, 0.f, 0.f};
    if (tid < 256) {
        float4 h04 = *(const float4*)(h0l + (size_t)ebg * HH + eog);
        hv[0] = h04.x; hv[1] = h04.y; hv[2] = h04.z; hv[3] = h04.w;
    }

    asm volatile("cp.async.wait_group 0;");
    __syncthreads();

    // Invariant ldsm per-lane bases.
    const int g  = lane >> 3;
    const int r8 = lane & 7;
    const int arow = wm + (g & 1) * 8 + r8;          // h row (batch)
    const int brow = wn + (g >> 1) * 8 + r8;         // Wh row
    const uint32_t aBase = smbase + HOFF + (uint32_t)arow * 2048;
    const uint32_t bBase = smbase + WOFF + (uint32_t)brow * 2048;
    const uint32_t arm = (uint32_t)(arow & 7);
    const uint32_t brm = (uint32_t)(brow & 7);
    const uint32_t ahalf = (uint32_t)(g >> 1);
    const uint32_t bhalf = (uint32_t)(g & 1);

    for (int t = 0; t < TT; t++) {
        const __half* hsrc = (t & 1) ? hBh : hAh;
        __half*       hnh  = (t & 1) ? hAh : hBh;

        // Prefetch xp for this step's epilogue (hidden under the GEMM).
        float4 xr4, xz4, xn4;
        if (tid < 256) {
            const float* xpr = xp + (size_t)t * BB * H3 + (size_t)ebg * H3 + eog;
            xr4 = *(const float4*)(xpr);
            xz4 = *(const float4*)(xpr + HH);
            xn4 = *(const float4*)(xpr + 2 * HH);
        }

        // Stream h tile: 2 commit groups of 64 rows x 64 chunks (64 KB each).
        #pragma unroll
        for (int p = 0; p < 2; p++) {
            for (int i = tid; i < 4096; i += 384) {
                int row = i >> 6;
                int c   = (p << 6) + (i & 63);
                const __half* src = hsrc + (size_t)(b0 + row) * HH + c * 8;
                uint32_t dst = smbase + HOFF + (uint32_t)row * 2048
                             + (uint32_t)((c ^ (row & 7)) << 4);
                asm volatile("cp.async.cg.shared.global [%0], [%1], 16;" :: "r"(dst), "l"(src));
            }
            asm volatile("cp.async.commit_group;");
        }

        float acc[2][4];
        #pragma unroll
        for (int nt = 0; nt < 2; nt++)
            #pragma unroll
            for (int c = 0; c < 4; c++) acc[nt][c] = 0.f;

        // Mainloop: 2 phases x 32 K16, barrier-free inside each phase.
        #pragma unroll 1
        for (int p = 0; p < 2; p++) {
            if (p == 0) asm volatile("cp.async.wait_group 1;");
            else        asm volatile("cp.async.wait_group 0;");
            __syncthreads();

            const int kt0 = p * 32;
            #pragma unroll
            for (int kk = 0; kk < 32; kk++) {
                uint32_t kt = (uint32_t)(kt0 + kk);
                uint32_t af[4], bf[4];
                uint32_t ca  = 2 * kt + ahalf;
                uint32_t cbk = 2 * kt + bhalf;
                ldsm4(af[0], af[1], af[2], af[3], aBase + ((ca ^ arm) << 4));
                ldsm4(bf[0], bf[1], bf[2], bf[3], bBase + ((cbk ^ brm) << 4));
                mma_f16(acc[0], af, &bf[0]);
                mma_f16(acc[1], af, &bf[2]);
            }
        }
        __syncthreads();   // fragment reads done -> safe to alias h region

        // Scatter accumulators: Cs[64][52] fp32, aliased onto h region.
        float* Cs = (float*)(dsm + HOFF);
        #pragma unroll
        for (int nt = 0; nt < 2; nt++) {
            int r = wm + (lane >> 2);
            int c = wn + nt * 8 + (lane & 3) * 2;
            Cs[r * 52 + c]           = acc[nt][0];
            Cs[r * 52 + c + 1]       = acc[nt][1];
            Cs[(r + 8) * 52 + c]     = acc[nt][2];
            Cs[(r + 8) * 52 + c + 1] = acc[nt][3];
        }
        __syncthreads();

        // Gate fusion: h carried in registers; writes y + fp16 h (+ hlast at end).
        if (tid < 256) {
            const float* bhn_s = (const float*)dsm;
            #pragma unroll
            for (int j = 0; j < 4; j++) {
                int u = eu0 + j;
                float hr = Cs[eb * 52 + 3 * u + 0];
                float hz = Cs[eb * 52 + 3 * u + 1];
                float hn = Cs[eb * 52 + 3 * u + 2] + bhn_s[u];
                float r  = 1.f / (1.f + __expf(-(((const float*)&xr4)[j] + hr)));
                float z  = 1.f / (1.f + __expf(-(((const float*)&xz4)[j] + hz)));
                float n  = tanhf(((const float*)&xn4)[j] + r * hn);
                hv[j] = (1.f - z) * n + z * hv[j];
            }
            *(float4*)(y + ((size_t)ebg * TT + t) * HH + eog) =
                make_float4(hv[0], hv[1], hv[2], hv[3]);
            *(uint2*)(hnh + (size_t)ebg * HH + eog) =
                make_uint2(pack_h2(hv[0], hv[1]), pack_h2(hv[2], hv[3]));
            if (t == TT - 1)
                *(float4*)(hlast + (size_t)ebg * HH + eog) =
                    make_float4(hv[0], hv[1], hv[2], hv[3]);
        }

        if (t + 1 < TT) grid_sync_dev();
    }
}

// ---------------------------------------------------------------------------
extern "C" void kernel_launch(void* const* d_in, const int* in_sizes, int n_in,
                              void* d_out, int out_size)
{
    (void)in_sizes; (void)n_in; (void)out_size;
    const float* x   = (const float*)d_in[0];  // [B,T,H]
    const float* h0  = (const float*)d_in[1];  // [L,B,H]
    const float* Wx  = (const float*)d_in[2];  // [L,3,H,H]
    const float* Wh  = (const float*)d_in[3];  // [L,3,H,H]
    const float* bx  = (const float*)d_in[4];  // [L,3,H]
    const float* bh  = (const float*)d_in[5];  // [L,3,H]
    float* out   = (float*)d_out;              // [B,T,H] then [L,B,H]
    float* hlast = out + (size_t)BB * TT * HH;

    float*  xp  = nullptr;
    __half* whh = nullptr;
    __half* hh  = nullptr;
    float*  gb  = nullptr;
    cudaGetSymbolAddress((void**)&xp,  g_xp);
    cudaGetSymbolAddress((void**)&whh, g_whh);
    cudaGetSymbolAddress((void**)&hh,  g_hh);
    cudaGetSymbolAddress((void**)&gb,  g_bias);
    __half* hAh = hh;
    __half* hBh = hh + BB * HH;

    cudaFuncSetAttribute(persist_kernel,
                         cudaFuncAttributeMaxDynamicSharedMemorySize, SMEM_TOT);

    // Pre-convert Wh to fp16; build combined xproj bias.
    {
        int n4 = 2 * 3 * HH * HH / 4;
        cvt_f16_kernel<<<n4 / 256, 256>>>(Wh, whh, n4);
        bias_kernel<<<(2 * H3 + 255) / 256, 256>>>(bx, bh, gb);
    }

    dim3 xgrid(H3 / 128, (BB * TT) / 128);  // (24, 128)
    dim3 pgrid(64, 2);                      // 128 CTAs

    for (int l = 0; l < 2; l++) {
        const float* cur = (l == 0) ? x : out;  // layer-1 input = layer-0 output
        xproj_kernel<<<xgrid, 256>>>(cur, Wx + (size_t)l * 3 * HH * HH,
                                     gb + (size_t)l * H3, xp);
        {
            int n4 = BB * HH / 4;
            cvt_f16_kernel<<<n4 / 256, 256>>>(h0 + (size_t)l * BB * HH, hAh, n4);
        }
        persist_kernel<<<pgrid, 384, SMEM_TOT>>>(
            whh + (size_t)l * 3 * HH * HH,
            bh + (size_t)l * H3 + 2 * HH,      // bh_n
            h0 + (size_t)l * BB * HH,
            xp, out,
            hlast + (size_t)l * BB * HH,
            hAh, hBh);
    }
}